// round 3
// baseline (speedup 1.0000x reference)
#include <cuda_runtime.h>

#define NPW      2048      // 65536 points / 32 bits
#define PTOT_MAX 512
#define BMAX     8
#define MAXP     128

__device__ unsigned g_pc_bits[PTOT_MAX * NPW];   // 4 MB bitmask: proposal x point
__device__ unsigned g_ref_bits[BMAX * NPW];      // per-scene reference cluster bitmask
__device__ int      g_ref_sum[BMAX];
__device__ int      g_offs[BMAX + 1];
__device__ float    g_iou[PTOT_MAX];
__device__ int      g_ctr;

// K_init: warp-ballot reference bitmask + popcount + offsets + counter reset.
// One thread per label; a warp covers 32 consecutive labels -> one bitmask word.
__global__ void k_init(const int* __restrict__ labels, const int* __restrict__ object_id,
                       const int* __restrict__ pes, int B, int npoint, int n_total) {
    int i = blockIdx.x * blockDim.x + threadIdx.x;
    if (i == 0) {
        g_offs[0] = 0;
        for (int b = 0; b < B; b++) g_offs[b + 1] = g_offs[b] + __ldg(&pes[b]);
        g_ctr = 0;
    }
    if (i < BMAX) g_ref_sum[i] = 0;
    if (i >= n_total) return;
    int b = i / npoint;                      // npoint is large; warp never straddles scenes
    int oid = __ldg(&object_id[b]);
    int match = (__ldg(&labels[i]) == oid) ? 1 : 0;
    unsigned bits = __ballot_sync(0xffffffffu, match);
    int lane = threadIdx.x & 31;
    int w = i >> 5;                          // global word index
    int local_w = w - b * (npoint >> 5);     // word within scene
    if (lane == 0) g_ref_bits[b * NPW + local_w] = bits;
    // warp-aggregated popcount into per-scene sum
    if (lane == 0) atomicAdd(&g_ref_sum[b], (int)__popc(bits));
}

// K_scatter: set bit (pid, j % npoint). 4 pairs per thread, pow2 fast path.
template <bool POW2>
__global__ void k_scatter4(const int4* __restrict__ pidx2, int M4, unsigned npoint, unsigned mask) {
    int i = blockIdx.x * blockDim.x + threadIdx.x;
    if (i >= M4) return;
    int4 a = __ldg(&pidx2[2 * i]);
    int4 b = __ldg(&pidx2[2 * i + 1]);
    unsigned j0, j1, j2, j3;
    if (POW2) {
        j0 = (unsigned)a.y & mask; j1 = (unsigned)a.w & mask;
        j2 = (unsigned)b.y & mask; j3 = (unsigned)b.w & mask;
    } else {
        j0 = (unsigned)a.y % npoint; j1 = (unsigned)a.w % npoint;
        j2 = (unsigned)b.y % npoint; j3 = (unsigned)b.w % npoint;
    }
    atomicOr(&g_pc_bits[(size_t)a.x * NPW + (j0 >> 5)], 1u << (j0 & 31u));
    atomicOr(&g_pc_bits[(size_t)a.z * NPW + (j1 >> 5)], 1u << (j1 & 31u));
    atomicOr(&g_pc_bits[(size_t)b.x * NPW + (j2 >> 5)], 1u << (j2 & 31u));
    atomicOr(&g_pc_bits[(size_t)b.z * NPW + (j3 >> 5)], 1u << (j3 & 31u));
}

// tail pairs (M % 4)
__global__ void k_scatter_tail(const int2* __restrict__ pidx, int start, int M, unsigned npoint) {
    int i = start + blockIdx.x * blockDim.x + threadIdx.x;
    if (i >= M) return;
    int2 v = __ldg(&pidx[i]);
    unsigned j = (unsigned)v.y % npoint;
    atomicOr(&g_pc_bits[(size_t)v.x * NPW + (j >> 5)], 1u << (j & 31u));
}

// K_reduce_final: warp per proposal (uint4 loads, MLP=16), last block writes outputs.
// Output layout (f32): [B*MAXP*C clus_feats | B*C select_feats | B sel_idx | B+1 offsets | B good]
__global__ void k_reduce_final(int B, int npw, int PTOT, int C,
                               const float* __restrict__ feats,
                               const int* __restrict__ pes,
                               float* __restrict__ out) {
    int lane = threadIdx.x & 31;
    int gw = (blockIdx.x * blockDim.x + threadIdx.x) >> 5;  // proposal id
    if (gw < PTOT) {
        int p = gw;
        int b = 0;
        #pragma unroll
        for (int k = 1; k <= BMAX; k++) b += (k <= B && g_offs[k] <= p) ? 1 : 0;
        if (b >= B) b = B - 1;
        const uint4* __restrict__ pcrow  = (const uint4*)(g_pc_bits + (size_t)p * NPW);
        const uint4* __restrict__ refrow = (const uint4*)(g_ref_bits + (size_t)b * NPW);
        int nq = npw >> 2;                 // uint4 chunks in a row
        unsigned cnt = 0, its = 0;
        #pragma unroll 16
        for (int w = lane; w < nq; w += 32) {
            uint4 v = __ldg(&pcrow[w]);
            uint4 r = __ldg(&refrow[w]);
            cnt += __popc(v.x) + __popc(v.y) + __popc(v.z) + __popc(v.w);
            its += __popc(v.x & r.x) + __popc(v.y & r.y)
                 + __popc(v.z & r.z) + __popc(v.w & r.w);
        }
        cnt = __reduce_add_sync(0xffffffffu, cnt);
        its = __reduce_add_sync(0xffffffffu, its);
        if (lane == 0) {
            float inter = (float)its;
            float uni = (float)cnt + (float)g_ref_sum[b] - inter;
            g_iou[p] = (uni > 0.0f) ? inter / fmaxf(uni, 1.0f) : 0.0f;
        }
    }
    // ---- last-block-done epilogue ----
    __syncthreads();
    __shared__ int s_last;
    if (threadIdx.x == 0) {
        __threadfence();
        s_last = (atomicAdd(&g_ctr, 1) == (int)gridDim.x - 1) ? 1 : 0;
    }
    __syncthreads();
    if (!s_last) return;

    __shared__ int   s_best[BMAX];
    __shared__ float s_max[BMAX];
    int tid = threadIdx.x;
    if (tid < B) {
        int lo = g_offs[tid], hi = g_offs[tid + 1];
        int best = -1; float mx = -1.0f;
        for (int p2 = lo; p2 < hi; p2++) {
            float v = g_iou[p2];
            if (v > mx) { mx = v; best = p2; }    // strict >: first max wins
        }
        s_best[tid] = (__ldg(&pes[tid]) > 0) ? best : -1;
        s_max[tid] = mx;
    }
    __syncthreads();
    int clus_n   = B * MAXP * C;
    int sf_off   = clus_n;
    int spi_off  = sf_off + B * C;
    int offs_off = spi_off + B;
    int good_off = offs_off + B + 1;
    int mc = MAXP * C;
    for (int idx = tid; idx < clus_n; idx += blockDim.x) {
        int b = idx / mc, rem = idx - b * mc;
        int slot = rem / C, c = rem - slot * C;
        int p = g_offs[b] + slot;
        float v = (p < g_offs[b + 1]) ? __ldg(&feats[(size_t)p * C + c]) : 0.0f;
        out[idx] = v;
    }
    for (int idx = tid; idx < B * C; idx += blockDim.x) {
        int b = idx / C, c = idx - b * C;
        int sel = s_best[b];
        out[sf_off + idx] = (sel >= 0) ? __ldg(&feats[(size_t)sel * C + c]) : 0.0f;
    }
    if (tid < B)  out[spi_off + tid]  = (float)s_best[tid];
    if (tid <= B) out[offs_off + tid] = (float)g_offs[tid];
    if (tid < B)  out[good_off + tid] = ((s_max[tid] > 0.2f) && (__ldg(&pes[tid]) > 0)) ? 1.0f : 0.0f;
}

extern "C" void kernel_launch(void* const* d_in, const int* in_sizes, int n_in,
                              void* d_out, int out_size) {
    const int*   pidx   = (const int*)d_in[0];   // [M,2] int32
    const int*   pes    = (const int*)d_in[1];   // [B] int32
    const int*   labels = (const int*)d_in[2];   // [B*npoint] int32
    const int*   oid    = (const int*)d_in[3];   // [B] int32
    const float* feats  = (const float*)d_in[4]; // [PTOT, C] f32
    float* out = (float*)d_out;

    int M       = in_sizes[0] / 2;
    int B       = in_sizes[1];
    int n_total = in_sizes[2];
    int npoint  = n_total / B;
    int C       = 32;
    int PTOT    = in_sizes[4] / C;
    int npw     = (npoint + 31) / 32;

    // zero the proposal bitmask via driver memset (one graph node)
    void* pc_ptr = nullptr;
    cudaGetSymbolAddress(&pc_ptr, g_pc_bits);
    cudaMemsetAsync(pc_ptr, 0, (size_t)PTOT * NPW * sizeof(unsigned), 0);

    k_init<<<(n_total + 255) / 256, 256>>>(labels, oid, pes, B, npoint, n_total);

    int M4 = M / 4;
    bool pow2 = (npoint & (npoint - 1)) == 0;
    if (M4 > 0) {
        if (pow2)
            k_scatter4<true><<<(M4 + 255) / 256, 256>>>((const int4*)pidx, M4,
                                                        (unsigned)npoint, (unsigned)(npoint - 1));
        else
            k_scatter4<false><<<(M4 + 255) / 256, 256>>>((const int4*)pidx, M4,
                                                         (unsigned)npoint, (unsigned)(npoint - 1));
    }
    if (M & 3)
        k_scatter_tail<<<1, 32>>>((const int2*)pidx, M4 * 4, M, (unsigned)npoint);

    int grid = (PTOT * 32 + 255) / 256;      // one warp per proposal
    k_reduce_final<<<grid, 256>>>(B, npw, PTOT, C, feats, pes, out);
}